// round 12
// baseline (speedup 1.0000x reference)
#include <cuda_runtime.h>
#include <cuda_fp16.h>
#include <math.h>
#include <stdint.h>

// ---------------- static config ----------------
#define TOK   100352          // 32 * 56 * 56 tokens
#define SCALE 0.17677669529663687f   // 32^-0.5

// ---------------- scratch (device globals; no allocs allowed) ----------------
__device__ __half g_a[TOK * 256];     // LN1-window output; reused: attention out, LN2 out
__device__ __half g_qkv[TOK * 768];   // QKV output
__device__ __half g_h[TOK * 1024];    // FC1/GELU output
__device__ __half g_wT[196608 + 65536 + 262144 + 262144];   // transposed half weights
__device__ __half g_bias[8 * 4 * 49 * 64];                  // bias+mask tables [h][cls][i][64]
#define OFF_QKVT 0
#define OFF_PROJT 196608
#define OFF_FC1T 262144
#define OFF_FC2T 524288

// ---------------- helpers ----------------
__device__ __forceinline__ float gelu_exact(float x)
{
    return 0.5f * x * (1.0f + erff(x * 0.70710678118654752f));
}

__device__ __forceinline__ int unshift_row(int mr)
{
    int ntok = mr % 49; int wb = mr / 49;
    int wwi = wb & 7, wh = (wb >> 3) & 7, b = wb >> 6;
    int r = ntok / 7, c = ntok % 7;
    int oh = wh * 7 + r + 3; if (oh >= 56) oh -= 56;
    int ow = wwi * 7 + c + 3; if (ow >= 56) ow -= 56;
    return b * 3136 + oh * 56 + ow;
}

__device__ __forceinline__ void cpa16(uint32_t dst, const void* src)
{
    asm volatile("cp.async.cg.shared.global [%0], [%1], 16;" :: "r"(dst), "l"(src));
}

__device__ __forceinline__ void ldsm4(uint32_t addr, uint32_t& r0, uint32_t& r1,
                                      uint32_t& r2, uint32_t& r3)
{
    asm volatile("ldmatrix.sync.aligned.m8n8.x4.shared.b16 {%0,%1,%2,%3}, [%4];"
                 : "=r"(r0), "=r"(r1), "=r"(r2), "=r"(r3) : "r"(addr));
}

__device__ __forceinline__ void ldsm4t(uint32_t addr, uint32_t& r0, uint32_t& r1,
                                       uint32_t& r2, uint32_t& r3)
{
    asm volatile("ldmatrix.sync.aligned.m8n8.x4.trans.shared.b16 {%0,%1,%2,%3}, [%4];"
                 : "=r"(r0), "=r"(r1), "=r"(r2), "=r"(r3) : "r"(addr));
}

__device__ __forceinline__ uint32_t packh2(float a, float b)
{
    __half2 h = __floats2half2_rn(a, b);
    return *(uint32_t*)&h;
}

#define MMA16816(C, A0, A1, A2, A3, B0, B1)                                 \
    asm volatile(                                                           \
        "mma.sync.aligned.m16n8k16.row.col.f32.f16.f16.f32 "                \
        "{%0,%1,%2,%3}, {%4,%5,%6,%7}, {%8,%9}, {%0,%1,%2,%3};"             \
        : "+f"((C)[0]), "+f"((C)[1]), "+f"((C)[2]), "+f"((C)[3])            \
        : "r"(A0), "r"(A1), "r"(A2), "r"(A3), "r"(B0), "r"(B1))

// ---------------- bias+mask table precompute ----------------
// table[h][cls][i][64], cls = (wh==7) | ((wwi==7)<<1). Cols >=49 get -10000.
__global__ void build_bias(const float* __restrict__ rpb, __half* __restrict__ table)
{
    int h = blockIdx.x, cls = blockIdx.y;
    int whTop = cls & 1, wwTop = (cls >> 1) & 1;
    for (int idx = threadIdx.x; idx < 49 * 64; idx += 256) {
        int i = idx >> 6, j = idx & 63;
        float v;
        if (j >= 49) {
            v = -10000.f;
        } else {
            int ri = i / 7, ci = i % 7, rj = j / 7, cj = j % 7;
            v = rpb[((ri - rj + 6) * 13 + (ci - cj + 6)) * 8 + h];
            int lri = whTop ? (ri < 4 ? 1 : 2) : 0;
            int lci = wwTop ? (ci < 4 ? 1 : 2) : 0;
            int lrj = whTop ? (rj < 4 ? 1 : 2) : 0;
            int lcj = wwTop ? (cj < 4 ? 1 : 2) : 0;
            if ((lri * 3 + lci) != (lrj * 3 + lcj)) v -= 100.f;
        }
        table[((h * 4 + cls) * 49 + i) * 64 + j] = __float2half_rn(v);
    }
}

// ---------------- merged weight transpose ----------------
__device__ __forceinline__ void tr_tile(const float* __restrict__ in, __half* __restrict__ out,
                                        int K, int N, int t)
{
    __shared__ float tbuf[32][33];
    int nx = N / 32;
    int bx = (t % nx) * 32;
    int by = (t / nx) * 32;
    int tx = threadIdx.x, ty = threadIdx.y;
#pragma unroll
    for (int i = 0; i < 32; i += 8)
        tbuf[ty + i][tx] = in[(size_t)(by + ty + i) * N + bx + tx];
    __syncthreads();
#pragma unroll
    for (int i = 0; i < 32; i += 8)
        out[(size_t)(bx + ty + i) * K + by + tx] = __float2half_rn(tbuf[tx][ty + i]);
}

__global__ void transpose_all(const float* __restrict__ qkv_w, const float* __restrict__ proj_w,
                              const float* __restrict__ fc1_w, const float* __restrict__ fc2_w,
                              __half* __restrict__ wT)
{
    int b = blockIdx.x;
    if (b < 192)        tr_tile(qkv_w,  wT + OFF_QKVT, 256, 768,  b);
    else if (b < 256)   tr_tile(proj_w, wT + OFF_PROJT, 256, 256, b - 192);
    else if (b < 512)   tr_tile(fc1_w,  wT + OFF_FC1T, 256, 1024, b - 256);
    else                tr_tile(fc2_w,  wT + OFF_FC2T, 1024, 256, b - 512);
}

// ---------------- LayerNorm (optionally fused shift+window gather), half out ----------
template<bool WIN>
__global__ void ln_kernel(const float* __restrict__ in, const float* __restrict__ gm,
                          const float* __restrict__ bt, __half* __restrict__ out)
{
    int gw   = (blockIdx.x * blockDim.x + threadIdx.x) >> 5;
    int lane = threadIdx.x & 31;
    if (gw >= TOK) return;

    const float* src;
    if (WIN) src = in + (size_t)unshift_row(gw) * 256;
    else     src = in + (size_t)gw * 256;

    float v[8];
#pragma unroll
    for (int i = 0; i < 8; i++) v[i] = src[lane + 32 * i];

    float s = 0.f;
#pragma unroll
    for (int i = 0; i < 8; i++) s += v[i];
#pragma unroll
    for (int o = 16; o > 0; o >>= 1) s += __shfl_xor_sync(0xffffffffu, s, o);
    float mean = s * (1.0f / 256.0f);

    float q = 0.f;
#pragma unroll
    for (int i = 0; i < 8; i++) { float d = v[i] - mean; q += d * d; }
#pragma unroll
    for (int o = 16; o > 0; o >>= 1) q += __shfl_xor_sync(0xffffffffu, q, o);
    float rstd = rsqrtf(q * (1.0f / 256.0f) + 1e-5f);

    __half* orow = out + (size_t)gw * 256;
#pragma unroll
    for (int i = 0; i < 8; i++) {
        int cc = lane + 32 * i;
        orow[cc] = __float2half_rn((v[i] - mean) * rstd * gm[cc] + bt[cc]);
    }
}

// ---------------- fp16 tensor-core GEMM (R10, unchanged) ----------------
template<int K, int NN, int MODE, typename OutT>
__global__ __launch_bounds__(128) void hgemm(
    const __half* __restrict__ A, const __half* __restrict__ BT,
    const float* __restrict__ bias, OutT* __restrict__ out,
    const float* __restrict__ res)
{
    extern __shared__ float smdyn[];
    const int tid  = threadIdx.x;
    const int lane = tid & 31;
    const int warp = tid >> 5;
    const int wm = warp >> 1, wn = warp & 1;
    const int bm = blockIdx.y, bn = blockIdx.x;

    const uint32_t sbase = (uint32_t)__cvta_generic_to_shared(smdyn);
    const uint32_t sA0 = sbase;
    const uint32_t sB0 = sbase + 32768;

    const int lr = tid >> 3;
    const int lg = tid & 7;
    const uint32_t swz = (uint32_t)((lg ^ (lr & 7)) << 4);
    const __half* Ag = A  + (size_t)(bm * 128 + lr) * K + lg * 8;
    const __half* Bg = BT + (size_t)(bn * 128 + lr) * K + lg * 8;
    const uint32_t dA = sA0 + lr * 128 + swz;
    const uint32_t dB = sB0 + lr * 128 + swz;

    float c[4][8][4];
#pragma unroll
    for (int i = 0; i < 4; i++)
#pragma unroll
        for (int j = 0; j < 8; j++)
#pragma unroll
            for (int l = 0; l < 4; l++) c[i][j][l] = 0.f;

#define PREF(KT_, BUF)                                                    \
    do {                                                                  \
        const __half* _a = Ag + (KT_) * 64;                               \
        const __half* _b = Bg + (KT_) * 64;                               \
        uint32_t _o = (BUF) * 16384;                                      \
        _Pragma("unroll")                                                 \
        for (int i = 0; i < 8; i++) {                                     \
            cpa16(dA + _o + i * 2048, _a + (size_t)i * 16 * K);           \
            cpa16(dB + _o + i * 2048, _b + (size_t)i * 16 * K);           \
        }                                                                 \
        asm volatile("cp.async.commit_group;");                           \
    } while (0)

    PREF(0, 0);
    asm volatile("cp.async.wait_group 0;");
    __syncthreads();

    const int l15 = lane & 15, hi = lane >> 4, l7 = lane & 7;
    uint32_t aRow[4], bRow[4];
#pragma unroll
    for (int mi = 0; mi < 4; mi++) aRow[mi] = sA0 + (uint32_t)((wm * 64 + mi * 16 + l15) * 128);
#pragma unroll
    for (int j = 0; j < 4; j++)    bRow[j]  = sB0 + (uint32_t)((wn * 64 + j * 16 + l15) * 128);

    int buf = 0;
    const int KT = K / 64;
#pragma unroll 1
    for (int kt = 0; kt < KT; kt++) {
        if (kt + 1 < KT) PREF(kt + 1, buf ^ 1);
        const uint32_t boff = (uint32_t)(buf * 16384);
#pragma unroll
        for (int ks = 0; ks < 4; ks++) {
            const uint32_t gph = (uint32_t)(((2 * ks + hi) ^ l7) << 4) + boff;
            uint32_t af[4][4], bq[4][4];
#pragma unroll
            for (int mi = 0; mi < 4; mi++)
                ldsm4(aRow[mi] + gph, af[mi][0], af[mi][1], af[mi][2], af[mi][3]);
#pragma unroll
            for (int j = 0; j < 4; j++)
                ldsm4(bRow[j] + gph, bq[j][0], bq[j][1], bq[j][2], bq[j][3]);
#pragma unroll
            for (int mi = 0; mi < 4; mi++)
#pragma unroll
                for (int ni = 0; ni < 8; ni++)
                    MMA16816(c[mi][ni], af[mi][0], af[mi][1], af[mi][2], af[mi][3],
                             bq[ni >> 1][ni & 1], bq[ni >> 1][2 + (ni & 1)]);
        }
        if (kt + 1 < KT) {
            asm volatile("cp.async.wait_group 0;");
            __syncthreads();
            buf ^= 1;
        }
    }
#undef PREF

#pragma unroll
    for (int mi = 0; mi < 4; mi++) {
        int mr0 = bm * 128 + wm * 64 + mi * 16 + (lane >> 2);
        int mr1 = mr0 + 8;
        size_t dst0, dst1;
        if (MODE == 1) { dst0 = (size_t)unshift_row(mr0); dst1 = (size_t)unshift_row(mr1); }
        else           { dst0 = (size_t)mr0;              dst1 = (size_t)mr1; }
#pragma unroll
        for (int ni = 0; ni < 8; ni++) {
            int col = bn * 128 + wn * 64 + ni * 8 + 2 * (lane & 3);
            float2 bb = *(const float2*)&bias[col];
            float2 o0, o1;
            o0.x = c[mi][ni][0] + bb.x; o0.y = c[mi][ni][1] + bb.y;
            o1.x = c[mi][ni][2] + bb.x; o1.y = c[mi][ni][3] + bb.y;
            if (MODE == 1 || MODE == 3) {
                float2 r0v = *(const float2*)&res[dst0 * NN + col];
                float2 r1v = *(const float2*)&res[dst1 * NN + col];
                o0.x += r0v.x; o0.y += r0v.y;
                o1.x += r1v.x; o1.y += r1v.y;
            }
            if (MODE == 2) {
                o0.x = gelu_exact(o0.x); o0.y = gelu_exact(o0.y);
                o1.x = gelu_exact(o1.x); o1.y = gelu_exact(o1.y);
            }
            if (MODE == 0 || MODE == 2) {
                *(__half2*)((__half*)out + dst0 * NN + col) = __floats2half2_rn(o0.x, o0.y);
                *(__half2*)((__half*)out + dst1 * NN + col) = __floats2half2_rn(o1.x, o1.y);
            } else {
                *(float2*)((float*)out + dst0 * NN + col) = o0;
                *(float2*)((float*)out + dst1 * NN + col) = o1;
            }
        }
    }
}

// ---------------- tensor-core windowed attention (table-bias version) ----------------
__global__ __launch_bounds__(128) void attn_mma(const __half* __restrict__ qkv,
                                                const __half* __restrict__ table,
                                                __half* __restrict__ out)
{
    const int wb = blockIdx.x;   // 0..2047
    const int h  = blockIdx.y;   // 0..7
    const int tid = threadIdx.x;
    const int lane = tid & 31;
    const int warp = tid >> 5;

    __shared__ __align__(16) __half sQ[64 * 40];
    __shared__ __align__(16) __half sK[64 * 40];
    __shared__ __align__(16) __half sV[64 * 40];

    // stage Q,K,V (49 rows x 32 halves, 16B chunks)
    for (int idx = tid; idx < 49 * 4; idx += 128) {
        int n = idx >> 2, c8 = idx & 3;
        const __half* src = qkv + (size_t)(wb * 49 + n) * 768 + h * 32 + c8 * 8;
        *(uint4*)&sQ[n * 40 + c8 * 8] = *(const uint4*)src;
        *(uint4*)&sK[n * 40 + c8 * 8] = *(const uint4*)(src + 256);
        *(uint4*)&sV[n * 40 + c8 * 8] = *(const uint4*)(src + 512);
    }
    for (int idx = tid; idx < 15 * 4; idx += 128) {
        int n = 49 + (idx >> 2), c8 = idx & 3;
        uint4 z = make_uint4(0, 0, 0, 0);
        *(uint4*)&sQ[n * 40 + c8 * 8] = z;
        *(uint4*)&sK[n * 40 + c8 * 8] = z;
        *(uint4*)&sV[n * 40 + c8 * 8] = z;
    }
    __syncthreads();

    const uint32_t sQb = (uint32_t)__cvta_generic_to_shared(sQ);
    const uint32_t sKb = (uint32_t)__cvta_generic_to_shared(sK);
    const uint32_t sVb = (uint32_t)__cvta_generic_to_shared(sV);
    const int l15 = lane & 15, hi = lane >> 4;

    // ---- scores S[16x64] = Q_band @ K^T ----
    float c[8][4];
#pragma unroll
    for (int nt = 0; nt < 8; nt++)
#pragma unroll
        for (int q = 0; q < 4; q++) c[nt][q] = 0.f;

    {
        uint32_t aq[2][4];
#pragma unroll
        for (int kc = 0; kc < 2; kc++)
            ldsm4(sQb + (uint32_t)((warp * 16 + l15) * 80 + (kc * 2 + hi) * 16),
                  aq[kc][0], aq[kc][1], aq[kc][2], aq[kc][3]);
#pragma unroll
        for (int kc = 0; kc < 2; kc++) {
            uint32_t bk[4][4];
#pragma unroll
            for (int jt = 0; jt < 4; jt++)
                ldsm4(sKb + (uint32_t)((jt * 16 + l15) * 80 + (kc * 2 + hi) * 16),
                      bk[jt][0], bk[jt][1], bk[jt][2], bk[jt][3]);
#pragma unroll
            for (int nt = 0; nt < 8; nt++)
                MMA16816(c[nt], aq[kc][0], aq[kc][1], aq[kc][2], aq[kc][3],
                         bk[nt >> 1][nt & 1], bk[nt >> 1][2 + (nt & 1)]);
        }
    }

    // ---- scale + bias + mask via precomputed table (fragment layout) ----
    const int cls = (int)(((wb >> 3) & 7) == 7) | (((int)((wb & 7) == 7)) << 1);
    const __half* tb = table + (size_t)((h * 4 + cls) * 49) * 64;
    const int iLo = warp * 16 + (lane >> 2);
    const int iHi = iLo + 8;
    const int jc = 2 * (lane & 3);
    const __half2* rowLo = (const __half2*)(tb + (iLo < 49 ? iLo : 0) * 64 + jc);
    const __half2* rowHi = (const __half2*)(tb + (iHi < 49 ? iHi : 0) * 64 + jc);

#pragma unroll
    for (int nt = 0; nt < 8; nt++) {
        float2 bL = __half22float2(rowLo[nt * 4]);
        float2 bH = __half22float2(rowHi[nt * 4]);
        c[nt][0] = c[nt][0] * SCALE + bL.x;
        c[nt][1] = c[nt][1] * SCALE + bL.y;
        c[nt][2] = c[nt][2] * SCALE + bH.x;
        c[nt][3] = c[nt][3] * SCALE + bH.y;
    }

    // ---- softmax per row (4 lanes per row: shfl xor 1,2) ----
    {
        float mxL = -1e30f, mxH = -1e30f;
#pragma unroll
        for (int nt = 0; nt < 8; nt++) {
            mxL = fmaxf(mxL, fmaxf(c[nt][0], c[nt][1]));
            mxH = fmaxf(mxH, fmaxf(c[nt][2], c[nt][3]));
        }
        mxL = fmaxf(mxL, __shfl_xor_sync(0xffffffffu, mxL, 1));
        mxL = fmaxf(mxL, __shfl_xor_sync(0xffffffffu, mxL, 2));
        mxH = fmaxf(mxH, __shfl_xor_sync(0xffffffffu, mxH, 1));
        mxH = fmaxf(mxH, __shfl_xor_sync(0xffffffffu, mxH, 2));
        float smL = 0.f, smH = 0.f;
#pragma unroll
        for (int nt = 0; nt < 8; nt++) {
            c[nt][0] = __expf(c[nt][0] - mxL); smL += c[nt][0];
            c[nt][1] = __expf(c[nt][1] - mxL); smL += c[nt][1];
            c[nt][2] = __expf(c[nt][2] - mxH); smH += c[nt][2];
            c[nt][3] = __expf(c[nt][3] - mxH); smH += c[nt][3];
        }
        smL += __shfl_xor_sync(0xffffffffu, smL, 1);
        smL += __shfl_xor_sync(0xffffffffu, smL, 2);
        smH += __shfl_xor_sync(0xffffffffu, smH, 1);
        smH += __shfl_xor_sync(0xffffffffu, smH, 2);
        float ivL = 1.0f / smL, ivH = 1.0f / smH;
#pragma unroll
        for (int nt = 0; nt < 8; nt++) {
            c[nt][0] *= ivL; c[nt][1] *= ivL;
            c[nt][2] *= ivH; c[nt][3] *= ivH;
        }
    }

    // ---- O[16x32] = P @ V ----
    float o[4][4];
#pragma unroll
    for (int nt = 0; nt < 4; nt++)
#pragma unroll
        for (int q = 0; q < 4; q++) o[nt][q] = 0.f;

#pragma unroll
    for (int kc2 = 0; kc2 < 4; kc2++) {
        uint32_t ap0 = packh2(c[2 * kc2][0],     c[2 * kc2][1]);
        uint32_t ap1 = packh2(c[2 * kc2][2],     c[2 * kc2][3]);
        uint32_t ap2 = packh2(c[2 * kc2 + 1][0], c[2 * kc2 + 1][1]);
        uint32_t ap3 = packh2(c[2 * kc2 + 1][2], c[2 * kc2 + 1][3]);
        uint32_t bv[2][4];
#pragma unroll
        for (int dp = 0; dp < 2; dp++)
            ldsm4t(sVb + (uint32_t)((kc2 * 16 + l15) * 80 + (dp * 2 + hi) * 16),
                   bv[dp][0], bv[dp][1], bv[dp][2], bv[dp][3]);
#pragma unroll
        for (int nt = 0; nt < 4; nt++)
            MMA16816(o[nt], ap0, ap1, ap2, ap3,
                     bv[nt >> 1][2 * (nt & 1)], bv[nt >> 1][2 * (nt & 1) + 1]);
    }

    // ---- write O rows < 49 ----
#pragma unroll
    for (int nt = 0; nt < 4; nt++) {
        int col = h * 32 + nt * 8 + 2 * (lane & 3);
        if (iLo < 49)
            *(__half2*)&out[(size_t)(wb * 49 + iLo) * 256 + col] =
                __floats2half2_rn(o[nt][0], o[nt][1]);
        if (iHi < 49)
            *(__half2*)&out[(size_t)(wb * 49 + iHi) * 256 + col] =
                __floats2half2_rn(o[nt][2], o[nt][3]);
    }
}

// ---------------- launch ----------------
extern "C" void kernel_launch(void* const* d_in, const int* in_sizes, int n_in,
                              void* d_out, int out_size)
{
    const float* x      = (const float*)d_in[0];
    const float* gamma1 = (const float*)d_in[1];
    const float* beta1  = (const float*)d_in[2];
    const float* qkv_w  = (const float*)d_in[3];
    const float* qkv_b  = (const float*)d_in[4];
    const float* proj_w = (const float*)d_in[5];
    const float* proj_b = (const float*)d_in[6];
    const float* rpb    = (const float*)d_in[7];
    const float* gamma2 = (const float*)d_in[8];
    const float* beta2  = (const float*)d_in[9];
    const float* fc1_w  = (const float*)d_in[10];
    const float* fc1_b  = (const float*)d_in[11];
    const float* fc2_w  = (const float*)d_in[12];
    const float* fc2_b  = (const float*)d_in[13];
    float* out = (float*)d_out;

    __half *pa, *pqkv, *ph, *pw, *pb;
    cudaGetSymbolAddress((void**)&pa, g_a);
    cudaGetSymbolAddress((void**)&pqkv, g_qkv);
    cudaGetSymbolAddress((void**)&ph, g_h);
    cudaGetSymbolAddress((void**)&pw, g_wT);
    cudaGetSymbolAddress((void**)&pb, g_bias);

    const int DSMEM = 65536;
    cudaFuncSetAttribute(hgemm<256, 768, 0, __half>,  cudaFuncAttributeMaxDynamicSharedMemorySize, DSMEM);
    cudaFuncSetAttribute(hgemm<256, 256, 1, float>,   cudaFuncAttributeMaxDynamicSharedMemorySize, DSMEM);
    cudaFuncSetAttribute(hgemm<256, 1024, 2, __half>, cudaFuncAttributeMaxDynamicSharedMemorySize, DSMEM);
    cudaFuncSetAttribute(hgemm<1024, 256, 3, float>,  cudaFuncAttributeMaxDynamicSharedMemorySize, DSMEM);

    // 0. transpose weights + build bias tables
    transpose_all<<<768, dim3(32, 8)>>>(qkv_w, proj_w, fc1_w, fc2_w, pw);
    build_bias<<<dim3(8, 4), 256>>>(rpb, pb);

    // 1. LN1 + cyclic shift + window partition -> g_a (half)
    ln_kernel<true><<<TOK / 8, 256>>>(x, gamma1, beta1, pa);
    // 2. QKV GEMM -> g_qkv (half)
    hgemm<256, 768, 0, __half><<<dim3(6, 784), 128, DSMEM>>>(pa, pw + OFF_QKVT, qkv_b, pqkv, nullptr);
    // 3. tensor-core attention (table bias) -> g_a (reused, half)
    attn_mma<<<dim3(2048, 8), 128>>>(pqkv, pb, pa);
    // 4. proj GEMM + window reverse + roll scatter + residual -> d_out (f32)
    hgemm<256, 256, 1, float><<<dim3(2, 784), 128, DSMEM>>>(pa, pw + OFF_PROJT, proj_b, out, x);
    // 5. LN2 -> g_a (reused, half)
    ln_kernel<false><<<TOK / 8, 256>>>(out, gamma2, beta2, pa);
    // 6. FC1 + GELU -> g_h (half)
    hgemm<256, 1024, 2, __half><<<dim3(8, 784), 128, DSMEM>>>(pa, pw + OFF_FC1T, fc1_b, ph, nullptr);
    // 7. FC2 + residual -> d_out (f32)
    hgemm<1024, 256, 3, float><<<dim3(2, 784), 128, DSMEM>>>(ph, pw + OFF_FC2T, fc2_b, out, out);
    (void)in_sizes; (void)n_in; (void)out_size;
}

// round 13
// speedup vs baseline: 1.0654x; 1.0654x over previous
#include <cuda_runtime.h>
#include <cuda_fp16.h>
#include <math.h>
#include <stdint.h>

// ---------------- static config ----------------
#define TOK   100352          // 32 * 56 * 56 tokens
#define SCALE 0.17677669529663687f   // 32^-0.5

// ---------------- scratch (device globals; no allocs allowed) ----------------
__device__ __half g_a[TOK * 256];     // LN1-window output; reused: attention out, LN2 out
__device__ __half g_qkv[TOK * 768];   // QKV output
__device__ __half g_h[TOK * 1024];    // FC1/GELU output
__device__ __half g_wT[196608 + 65536 + 262144 + 262144];   // transposed half weights
#define OFF_QKVT 0
#define OFF_PROJT 196608
#define OFF_FC1T 262144
#define OFF_FC2T 524288

// ---------------- helpers ----------------
__device__ __forceinline__ float gelu_exact(float x)
{
    return 0.5f * x * (1.0f + erff(x * 0.70710678118654752f));
}

__device__ __forceinline__ int unshift_row(int mr)
{
    int ntok = mr % 49; int wb = mr / 49;
    int wwi = wb & 7, wh = (wb >> 3) & 7, b = wb >> 6;
    int r = ntok / 7, c = ntok % 7;
    int oh = wh * 7 + r + 3; if (oh >= 56) oh -= 56;
    int ow = wwi * 7 + c + 3; if (ow >= 56) ow -= 56;
    return b * 3136 + oh * 56 + ow;
}

__device__ __forceinline__ void cpa16(uint32_t dst, const void* src)
{
    asm volatile("cp.async.cg.shared.global [%0], [%1], 16;" :: "r"(dst), "l"(src));
}

__device__ __forceinline__ void ldsm4(uint32_t addr, uint32_t& r0, uint32_t& r1,
                                      uint32_t& r2, uint32_t& r3)
{
    asm volatile("ldmatrix.sync.aligned.m8n8.x4.shared.b16 {%0,%1,%2,%3}, [%4];"
                 : "=r"(r0), "=r"(r1), "=r"(r2), "=r"(r3) : "r"(addr));
}

__device__ __forceinline__ void ldsm4t(uint32_t addr, uint32_t& r0, uint32_t& r1,
                                       uint32_t& r2, uint32_t& r3)
{
    asm volatile("ldmatrix.sync.aligned.m8n8.x4.trans.shared.b16 {%0,%1,%2,%3}, [%4];"
                 : "=r"(r0), "=r"(r1), "=r"(r2), "=r"(r3) : "r"(addr));
}

__device__ __forceinline__ uint32_t packh2(float a, float b)
{
    __half2 h = __floats2half2_rn(a, b);
    return *(uint32_t*)&h;
}

#define MMA16816(C, A0, A1, A2, A3, B0, B1)                                 \
    asm volatile(                                                           \
        "mma.sync.aligned.m16n8k16.row.col.f32.f16.f16.f32 "                \
        "{%0,%1,%2,%3}, {%4,%5,%6,%7}, {%8,%9}, {%0,%1,%2,%3};"             \
        : "+f"((C)[0]), "+f"((C)[1]), "+f"((C)[2]), "+f"((C)[3])            \
        : "r"(A0), "r"(A1), "r"(A2), "r"(A3), "r"(B0), "r"(B1))

// ---------------- merged weight transpose ----------------
__device__ __forceinline__ void tr_tile(const float* __restrict__ in, __half* __restrict__ out,
                                        int K, int N, int t)
{
    __shared__ float tbuf[32][33];
    int nx = N / 32;
    int bx = (t % nx) * 32;
    int by = (t / nx) * 32;
    int tx = threadIdx.x, ty = threadIdx.y;
#pragma unroll
    for (int i = 0; i < 32; i += 8)
        tbuf[ty + i][tx] = in[(size_t)(by + ty + i) * N + bx + tx];
    __syncthreads();
#pragma unroll
    for (int i = 0; i < 32; i += 8)
        out[(size_t)(bx + ty + i) * K + by + tx] = __float2half_rn(tbuf[tx][ty + i]);
}

__global__ void transpose_all(const float* __restrict__ qkv_w, const float* __restrict__ proj_w,
                              const float* __restrict__ fc1_w, const float* __restrict__ fc2_w,
                              __half* __restrict__ wT)
{
    int b = blockIdx.x;
    if (b < 192)        tr_tile(qkv_w,  wT + OFF_QKVT, 256, 768,  b);
    else if (b < 256)   tr_tile(proj_w, wT + OFF_PROJT, 256, 256, b - 192);
    else if (b < 512)   tr_tile(fc1_w,  wT + OFF_FC1T, 256, 1024, b - 256);
    else                tr_tile(fc2_w,  wT + OFF_FC2T, 1024, 256, b - 512);
}

// ---------------- LayerNorm (optionally fused shift+window gather), half out ----------
template<bool WIN>
__global__ void ln_kernel(const float* __restrict__ in, const float* __restrict__ gm,
                          const float* __restrict__ bt, __half* __restrict__ out)
{
    int gw   = (blockIdx.x * blockDim.x + threadIdx.x) >> 5;
    int lane = threadIdx.x & 31;
    if (gw >= TOK) return;

    const float* src;
    if (WIN) src = in + (size_t)unshift_row(gw) * 256;
    else     src = in + (size_t)gw * 256;

    float v[8];
#pragma unroll
    for (int i = 0; i < 8; i++) v[i] = src[lane + 32 * i];

    float s = 0.f;
#pragma unroll
    for (int i = 0; i < 8; i++) s += v[i];
#pragma unroll
    for (int o = 16; o > 0; o >>= 1) s += __shfl_xor_sync(0xffffffffu, s, o);
    float mean = s * (1.0f / 256.0f);

    float q = 0.f;
#pragma unroll
    for (int i = 0; i < 8; i++) { float d = v[i] - mean; q += d * d; }
#pragma unroll
    for (int o = 16; o > 0; o >>= 1) q += __shfl_xor_sync(0xffffffffu, q, o);
    float rstd = rsqrtf(q * (1.0f / 256.0f) + 1e-5f);

    __half* orow = out + (size_t)gw * 256;
#pragma unroll
    for (int i = 0; i < 8; i++) {
        int cc = lane + 32 * i;
        orow[cc] = __float2half_rn((v[i] - mean) * rstd * gm[cc] + bt[cc]);
    }
}

// ---------------- fp16 tensor-core GEMM (R10 + 3-CTA register cap) ----------------
template<int K, int NN, int MODE, typename OutT>
__global__ __launch_bounds__(128, 3) void hgemm(
    const __half* __restrict__ A, const __half* __restrict__ BT,
    const float* __restrict__ bias, OutT* __restrict__ out,
    const float* __restrict__ res)
{
    extern __shared__ float smdyn[];
    const int tid  = threadIdx.x;
    const int lane = tid & 31;
    const int warp = tid >> 5;
    const int wm = warp >> 1, wn = warp & 1;
    const int bm = blockIdx.y, bn = blockIdx.x;

    const uint32_t sbase = (uint32_t)__cvta_generic_to_shared(smdyn);
    const uint32_t sA0 = sbase;
    const uint32_t sB0 = sbase + 32768;

    const int lr = tid >> 3;
    const int lg = tid & 7;
    const uint32_t swz = (uint32_t)((lg ^ (lr & 7)) << 4);
    const __half* Ag = A  + (size_t)(bm * 128 + lr) * K + lg * 8;
    const __half* Bg = BT + (size_t)(bn * 128 + lr) * K + lg * 8;
    const uint32_t dA = sA0 + lr * 128 + swz;
    const uint32_t dB = sB0 + lr * 128 + swz;

    float c[4][8][4];
#pragma unroll
    for (int i = 0; i < 4; i++)
#pragma unroll
        for (int j = 0; j < 8; j++)
#pragma unroll
            for (int l = 0; l < 4; l++) c[i][j][l] = 0.f;

#define PREF(KT_, BUF)                                                    \
    do {                                                                  \
        const __half* _a = Ag + (KT_) * 64;                               \
        const __half* _b = Bg + (KT_) * 64;                               \
        uint32_t _o = (BUF) * 16384;                                      \
        _Pragma("unroll")                                                 \
        for (int i = 0; i < 8; i++) {                                     \
            cpa16(dA + _o + i * 2048, _a + (size_t)i * 16 * K);           \
            cpa16(dB + _o + i * 2048, _b + (size_t)i * 16 * K);           \
        }                                                                 \
        asm volatile("cp.async.commit_group;");                           \
    } while (0)

    PREF(0, 0);
    asm volatile("cp.async.wait_group 0;");
    __syncthreads();

    const int l15 = lane & 15, hi = lane >> 4, l7 = lane & 7;
    uint32_t aRow[4], bRow[4];
#pragma unroll
    for (int mi = 0; mi < 4; mi++) aRow[mi] = sA0 + (uint32_t)((wm * 64 + mi * 16 + l15) * 128);
#pragma unroll
    for (int j = 0; j < 4; j++)    bRow[j]  = sB0 + (uint32_t)((wn * 64 + j * 16 + l15) * 128);

    int buf = 0;
    const int KT = K / 64;
#pragma unroll 1
    for (int kt = 0; kt < KT; kt++) {
        if (kt + 1 < KT) PREF(kt + 1, buf ^ 1);
        const uint32_t boff = (uint32_t)(buf * 16384);
#pragma unroll
        for (int ks = 0; ks < 4; ks++) {
            const uint32_t gph = (uint32_t)(((2 * ks + hi) ^ l7) << 4) + boff;
            uint32_t af[4][4], bq[4][4];
#pragma unroll
            for (int mi = 0; mi < 4; mi++)
                ldsm4(aRow[mi] + gph, af[mi][0], af[mi][1], af[mi][2], af[mi][3]);
#pragma unroll
            for (int j = 0; j < 4; j++)
                ldsm4(bRow[j] + gph, bq[j][0], bq[j][1], bq[j][2], bq[j][3]);
#pragma unroll
            for (int mi = 0; mi < 4; mi++)
#pragma unroll
                for (int ni = 0; ni < 8; ni++)
                    MMA16816(c[mi][ni], af[mi][0], af[mi][1], af[mi][2], af[mi][3],
                             bq[ni >> 1][ni & 1], bq[ni >> 1][2 + (ni & 1)]);
        }
        if (kt + 1 < KT) {
            asm volatile("cp.async.wait_group 0;");
            __syncthreads();
            buf ^= 1;
        }
    }
#undef PREF

#pragma unroll
    for (int mi = 0; mi < 4; mi++) {
        int mr0 = bm * 128 + wm * 64 + mi * 16 + (lane >> 2);
        int mr1 = mr0 + 8;
        size_t dst0, dst1;
        if (MODE == 1) { dst0 = (size_t)unshift_row(mr0); dst1 = (size_t)unshift_row(mr1); }
        else           { dst0 = (size_t)mr0;              dst1 = (size_t)mr1; }
#pragma unroll
        for (int ni = 0; ni < 8; ni++) {
            int col = bn * 128 + wn * 64 + ni * 8 + 2 * (lane & 3);
            float2 bb = *(const float2*)&bias[col];
            float2 o0, o1;
            o0.x = c[mi][ni][0] + bb.x; o0.y = c[mi][ni][1] + bb.y;
            o1.x = c[mi][ni][2] + bb.x; o1.y = c[mi][ni][3] + bb.y;
            if (MODE == 1 || MODE == 3) {
                float2 r0v = *(const float2*)&res[dst0 * NN + col];
                float2 r1v = *(const float2*)&res[dst1 * NN + col];
                o0.x += r0v.x; o0.y += r0v.y;
                o1.x += r1v.x; o1.y += r1v.y;
            }
            if (MODE == 2) {
                o0.x = gelu_exact(o0.x); o0.y = gelu_exact(o0.y);
                o1.x = gelu_exact(o1.x); o1.y = gelu_exact(o1.y);
            }
            if (MODE == 0 || MODE == 2) {
                *(__half2*)((__half*)out + dst0 * NN + col) = __floats2half2_rn(o0.x, o0.y);
                *(__half2*)((__half*)out + dst1 * NN + col) = __floats2half2_rn(o1.x, o1.y);
            } else {
                *(float2*)((float*)out + dst0 * NN + col) = o0;
                *(float2*)((float*)out + dst1 * NN + col) = o1;
            }
        }
    }
}

// ---------------- tensor-core windowed attention (R11 meta version) ----------------
__global__ __launch_bounds__(128) void attn_mma(const __half* __restrict__ qkv,
                                                const float* __restrict__ rpb,
                                                __half* __restrict__ out)
{
    const int wb = blockIdx.x;   // 0..2047
    const int h  = blockIdx.y;   // 0..7
    const int tid = threadIdx.x;
    const int lane = tid & 31;
    const int warp = tid >> 5;

    __shared__ __align__(16) __half sQ[64 * 40];
    __shared__ __align__(16) __half sK[64 * 40];
    __shared__ __align__(16) __half sV[64 * 40];
    __shared__ float rpb_s[169];
    __shared__ int meta[49];     // (lab<<8) | (r<<4) | c

    for (int idx = tid; idx < 49 * 4; idx += 128) {
        int n = idx >> 2, c8 = idx & 3;
        const __half* src = qkv + (size_t)(wb * 49 + n) * 768 + h * 32 + c8 * 8;
        *(uint4*)&sQ[n * 40 + c8 * 8] = *(const uint4*)src;
        *(uint4*)&sK[n * 40 + c8 * 8] = *(const uint4*)(src + 256);
        *(uint4*)&sV[n * 40 + c8 * 8] = *(const uint4*)(src + 512);
    }
    for (int idx = tid; idx < 15 * 4; idx += 128) {
        int n = 49 + (idx >> 2), c8 = idx & 3;
        uint4 z = make_uint4(0, 0, 0, 0);
        *(uint4*)&sQ[n * 40 + c8 * 8] = z;
        *(uint4*)&sK[n * 40 + c8 * 8] = z;
        *(uint4*)&sV[n * 40 + c8 * 8] = z;
    }
    for (int i = tid; i < 169; i += 128) rpb_s[i] = rpb[i * 8 + h];
    if (tid < 49) {
        int wwi = wb & 7, wh = (wb >> 3) & 7;
        int r = tid / 7, c = tid % 7;
        int gr = wh * 7 + r, gc = wwi * 7 + c;
        int lr = gr < 49 ? 0 : (gr < 53 ? 1 : 2);
        int lc = gc < 49 ? 0 : (gc < 53 ? 1 : 2);
        meta[tid] = ((lr * 3 + lc) << 8) | (r << 4) | c;
    }
    __syncthreads();

    const uint32_t sQb = (uint32_t)__cvta_generic_to_shared(sQ);
    const uint32_t sKb = (uint32_t)__cvta_generic_to_shared(sK);
    const uint32_t sVb = (uint32_t)__cvta_generic_to_shared(sV);
    const int l15 = lane & 15, hi = lane >> 4;

    float c[8][4];
#pragma unroll
    for (int nt = 0; nt < 8; nt++)
#pragma unroll
        for (int q = 0; q < 4; q++) c[nt][q] = 0.f;

    {
        uint32_t aq[2][4];
#pragma unroll
        for (int kc = 0; kc < 2; kc++)
            ldsm4(sQb + (uint32_t)((warp * 16 + l15) * 80 + (kc * 2 + hi) * 16),
                  aq[kc][0], aq[kc][1], aq[kc][2], aq[kc][3]);
#pragma unroll
        for (int kc = 0; kc < 2; kc++) {
            uint32_t bk[4][4];
#pragma unroll
            for (int jt = 0; jt < 4; jt++)
                ldsm4(sKb + (uint32_t)((jt * 16 + l15) * 80 + (kc * 2 + hi) * 16),
                      bk[jt][0], bk[jt][1], bk[jt][2], bk[jt][3]);
#pragma unroll
            for (int nt = 0; nt < 8; nt++)
                MMA16816(c[nt], aq[kc][0], aq[kc][1], aq[kc][2], aq[kc][3],
                         bk[nt >> 1][nt & 1], bk[nt >> 1][2 + (nt & 1)]);
        }
    }

    const int iLo = warp * 16 + (lane >> 2);
    const int iHi = iLo + 8;
    const int mLo = (iLo < 49) ? meta[iLo] : 0;
    const int mHi = (iHi < 49) ? meta[iHi] : 0;
    const int riL = (mLo >> 4) & 15, ciL = mLo & 15, lbL = mLo >> 8;
    const int riH = (mHi >> 4) & 15, ciH = mHi & 15, lbH = mHi >> 8;

#pragma unroll
    for (int nt = 0; nt < 8; nt++) {
#pragma unroll
        for (int q = 0; q < 2; q++) {
            int j = nt * 8 + 2 * (lane & 3) + q;
            if (j < 49) {
                int mj = meta[j];
                int rj = (mj >> 4) & 15, cj = mj & 15, lbj = mj >> 8;
                float bL = rpb_s[(riL - rj + 6) * 13 + (ciL - cj + 6)];
                float bH = rpb_s[(riH - rj + 6) * 13 + (ciH - cj + 6)];
                float sL = c[nt][q] * SCALE + bL;
                float sH = c[nt][2 + q] * SCALE + bH;
                if (lbL != lbj) sL -= 100.f;
                if (lbH != lbj) sH -= 100.f;
                c[nt][q] = sL;
                c[nt][2 + q] = sH;
            } else {
                c[nt][q] = -10000.f;
                c[nt][2 + q] = -10000.f;
            }
        }
    }

    {
        float mxL = -1e30f, mxH = -1e30f;
#pragma unroll
        for (int nt = 0; nt < 8; nt++) {
            mxL = fmaxf(mxL, fmaxf(c[nt][0], c[nt][1]));
            mxH = fmaxf(mxH, fmaxf(c[nt][2], c[nt][3]));
        }
        mxL = fmaxf(mxL, __shfl_xor_sync(0xffffffffu, mxL, 1));
        mxL = fmaxf(mxL, __shfl_xor_sync(0xffffffffu, mxL, 2));
        mxH = fmaxf(mxH, __shfl_xor_sync(0xffffffffu, mxH, 1));
        mxH = fmaxf(mxH, __shfl_xor_sync(0xffffffffu, mxH, 2));
        float smL = 0.f, smH = 0.f;
#pragma unroll
        for (int nt = 0; nt < 8; nt++) {
            c[nt][0] = __expf(c[nt][0] - mxL); smL += c[nt][0];
            c[nt][1] = __expf(c[nt][1] - mxL); smL += c[nt][1];
            c[nt][2] = __expf(c[nt][2] - mxH); smH += c[nt][2];
            c[nt][3] = __expf(c[nt][3] - mxH); smH += c[nt][3];
        }
        smL += __shfl_xor_sync(0xffffffffu, smL, 1);
        smL += __shfl_xor_sync(0xffffffffu, smL, 2);
        smH += __shfl_xor_sync(0xffffffffu, smH, 1);
        smH += __shfl_xor_sync(0xffffffffu, smH, 2);
        float ivL = 1.0f / smL, ivH = 1.0f / smH;
#pragma unroll
        for (int nt = 0; nt < 8; nt++) {
            c[nt][0] *= ivL; c[nt][1] *= ivL;
            c[nt][2] *= ivH; c[nt][3] *= ivH;
        }
    }

    float o[4][4];
#pragma unroll
    for (int nt = 0; nt < 4; nt++)
#pragma unroll
        for (int q = 0; q < 4; q++) o[nt][q] = 0.f;

#pragma unroll
    for (int kc2 = 0; kc2 < 4; kc2++) {
        uint32_t ap0 = packh2(c[2 * kc2][0],     c[2 * kc2][1]);
        uint32_t ap1 = packh2(c[2 * kc2][2],     c[2 * kc2][3]);
        uint32_t ap2 = packh2(c[2 * kc2 + 1][0], c[2 * kc2 + 1][1]);
        uint32_t ap3 = packh2(c[2 * kc2 + 1][2], c[2 * kc2 + 1][3]);
        uint32_t bv[2][4];
#pragma unroll
        for (int dp = 0; dp < 2; dp++)
            ldsm4t(sVb + (uint32_t)((kc2 * 16 + l15) * 80 + (dp * 2 + hi) * 16),
                   bv[dp][0], bv[dp][1], bv[dp][2], bv[dp][3]);
#pragma unroll
        for (int nt = 0; nt < 4; nt++)
            MMA16816(o[nt], ap0, ap1, ap2, ap3,
                     bv[nt >> 1][2 * (nt & 1)], bv[nt >> 1][2 * (nt & 1) + 1]);
    }

#pragma unroll
    for (int nt = 0; nt < 4; nt++) {
        int col = h * 32 + nt * 8 + 2 * (lane & 3);
        if (iLo < 49)
            *(__half2*)&out[(size_t)(wb * 49 + iLo) * 256 + col] =
                __floats2half2_rn(o[nt][0], o[nt][1]);
        if (iHi < 49)
            *(__half2*)&out[(size_t)(wb * 49 + iHi) * 256 + col] =
                __floats2half2_rn(o[nt][2], o[nt][3]);
    }
}

// ---------------- launch ----------------
extern "C" void kernel_launch(void* const* d_in, const int* in_sizes, int n_in,
                              void* d_out, int out_size)
{
    const float* x      = (const float*)d_in[0];
    const float* gamma1 = (const float*)d_in[1];
    const float* beta1  = (const float*)d_in[2];
    const float* qkv_w  = (const float*)d_in[3];
    const float* qkv_b  = (const float*)d_in[4];
    const float* proj_w = (const float*)d_in[5];
    const float* proj_b = (const float*)d_in[6];
    const float* rpb    = (const float*)d_in[7];
    const float* gamma2 = (const float*)d_in[8];
    const float* beta2  = (const float*)d_in[9];
    const float* fc1_w  = (const float*)d_in[10];
    const float* fc1_b  = (const float*)d_in[11];
    const float* fc2_w  = (const float*)d_in[12];
    const float* fc2_b  = (const float*)d_in[13];
    float* out = (float*)d_out;

    __half *pa, *pqkv, *ph, *pw;
    cudaGetSymbolAddress((void**)&pa, g_a);
    cudaGetSymbolAddress((void**)&pqkv, g_qkv);
    cudaGetSymbolAddress((void**)&ph, g_h);
    cudaGetSymbolAddress((void**)&pw, g_wT);

    const int DSMEM = 65536;
    cudaFuncSetAttribute(hgemm<256, 768, 0, __half>,  cudaFuncAttributeMaxDynamicSharedMemorySize, DSMEM);
    cudaFuncSetAttribute(hgemm<256, 256, 1, float>,   cudaFuncAttributeMaxDynamicSharedMemorySize, DSMEM);
    cudaFuncSetAttribute(hgemm<256, 1024, 2, __half>, cudaFuncAttributeMaxDynamicSharedMemorySize, DSMEM);
    cudaFuncSetAttribute(hgemm<1024, 256, 3, float>,  cudaFuncAttributeMaxDynamicSharedMemorySize, DSMEM);

    // 0. transpose + half-round all weights (single launch)
    transpose_all<<<768, dim3(32, 8)>>>(qkv_w, proj_w, fc1_w, fc2_w, pw);

    // 1. LN1 + cyclic shift + window partition -> g_a (half)
    ln_kernel<true><<<TOK / 8, 256>>>(x, gamma1, beta1, pa);
    // 2. QKV GEMM -> g_qkv (half)
    hgemm<256, 768, 0, __half><<<dim3(6, 784), 128, DSMEM>>>(pa, pw + OFF_QKVT, qkv_b, pqkv, nullptr);
    // 3. tensor-core attention -> g_a (reused, half)
    attn_mma<<<dim3(2048, 8), 128>>>(pqkv, rpb, pa);
    // 4. proj GEMM + window reverse + roll scatter + residual -> d_out (f32)
    hgemm<256, 256, 1, float><<<dim3(2, 784), 128, DSMEM>>>(pa, pw + OFF_PROJT, proj_b, out, x);
    // 5. LN2 -> g_a (reused, half)
    ln_kernel<false><<<TOK / 8, 256>>>(out, gamma2, beta2, pa);
    // 6. FC1 + GELU -> g_h (half)
    hgemm<256, 1024, 2, __half><<<dim3(8, 784), 128, DSMEM>>>(pa, pw + OFF_FC1T, fc1_b, ph, nullptr);
    // 7. FC2 + residual -> d_out (f32)
    hgemm<1024, 256, 3, float><<<dim3(2, 784), 128, DSMEM>>>(ph, pw + OFF_FC2T, fc2_b, out, out);
    (void)in_sizes; (void)n_in; (void)out_size;
}